// round 6
// baseline (speedup 1.0000x reference)
#include <cuda_runtime.h>
#include <cstdint>

#define IMG_S 128
#define NPIX (IMG_S * IMG_S)
#define MAXF 4096
#define Z_NEAR 0.1f
#define Z_FAR 100.0f

#define NBLK 148
#define NTHR 512
#define NWARPS ((NBLK * NTHR) / 32)
#define LOSS_BLKS 8   // 8 blocks x 512 threads x 1 float4 = 4096 float4 = NPIX

// ---- scratch (zero-initialized at module load; we restore zeros each run) ----
__device__ unsigned long long g_zbuf[NPIX];   // 0 == empty (inverted-key encoding)
__device__ float4 g_colors[MAXF];
__device__ float g_gray[NPIX];
__device__ float g_slot_max[NBLK];
__device__ float g_slot_msk[NBLK];
__device__ float g_slot_s1[LOSS_BLKS];
__device__ unsigned int g_bar_count[3];
__device__ unsigned int g_bar_gen[3];

// ---------------------------------------------------------------------------
// Grid barrier, safe across graph replays (generation flag read at entry;
// counter reset by last arriver BEFORE flag release). Requires co-residency,
// guaranteed by __launch_bounds__(NTHR, 2) with grid == 148 <= SM count.
__device__ __forceinline__ void grid_barrier(int k) {
    __threadfence();
    __syncthreads();
    if (threadIdx.x == 0) {
        unsigned int gen = *((volatile unsigned int*)&g_bar_gen[k]);
        unsigned int old = atomicAdd(&g_bar_count[k], 1u);
        if (old == NBLK - 1) {
            g_bar_count[k] = 0;           // reset for next replay
            __threadfence();
            atomicAdd(&g_bar_gen[k], 1u); // release
        } else {
            while (*((volatile unsigned int*)&g_bar_gen[k]) == gen) {}
        }
    }
    __syncthreads();
    __threadfence();
}

// ---------------------------------------------------------------------------
__device__ __forceinline__ float3 project_vert(float3 p,
                                               const float* __restrict__ R,
                                               const float* __restrict__ t,
                                               const float* __restrict__ K) {
    float vx = R[0] * p.x + R[1] * p.y + R[2] * p.z + t[0];
    float vy = R[3] * p.x + R[4] * p.y + R[5] * p.z + t[1];
    float vz = R[6] * p.x + R[7] * p.y + R[8] * p.z + t[2];
    float zd = vz + 1e-9f;
    float xn = vx / zd;
    float yn = vy / zd;
    float u = K[0] * xn + K[1] * yn + K[2];
    float v = K[3] * xn + K[4] * yn + K[5];
    float S = (float)IMG_S;
    float uu  = 2.0f * (u - S * 0.5f) / S;
    float vfl = S - v;
    float vvn = 2.0f * (vfl - S * 0.5f) / S;
    return make_float3(uu, vvn, vz);
}

// ---------------------------------------------------------------------------
__device__ void raster_face(int f,
                            const float* __restrict__ verts,
                            const int*   __restrict__ faces,
                            const float* __restrict__ tex,
                            const float* __restrict__ R,
                            const float* __restrict__ t,
                            const float* __restrict__ K,
                            const float* __restrict__ Ldir,
                            float idir, float iamb, int lane) {
    int i0 = faces[3 * f + 0];
    int i1 = faces[3 * f + 1];
    int i2 = faces[3 * f + 2];

    float3 A = make_float3(verts[3 * i0], verts[3 * i0 + 1], verts[3 * i0 + 2]);
    float3 B = make_float3(verts[3 * i1], verts[3 * i1 + 1], verts[3 * i1 + 2]);
    float3 C = make_float3(verts[3 * i2], verts[3 * i2 + 1], verts[3 * i2 + 2]);

    // ---- lighting (world space) ----
    float3 v10 = make_float3(A.x - B.x, A.y - B.y, A.z - B.z);
    float3 v12 = make_float3(C.x - B.x, C.y - B.y, C.z - B.z);
    float nx = v10.y * v12.z - v10.z * v12.y;
    float ny = v10.z * v12.x - v10.x * v12.z;
    float nz = v10.x * v12.y - v10.y * v12.x;
    float nrm = sqrtf(nx * nx + ny * ny + nz * nz);
    float inv = 1.0f / fmaxf(nrm, 1e-5f);
    nx *= inv; ny *= inv; nz *= inv;
    float cosv = fmaxf(0.0f, nx * Ldir[0] + ny * Ldir[1] + nz * Ldir[2]);
    float light = iamb + idir * cosv;
    if (lane == 0) {
        g_colors[f] = make_float4(tex[3 * f + 0] * light,
                                  tex[3 * f + 1] * light,
                                  tex[3 * f + 2] * light, 0.0f);
    }

    // ---- projection ----
    float3 p0 = project_vert(A, R, t, K);
    float3 p1 = project_vert(B, R, t, K);
    float3 p2 = project_vert(C, R, t, K);
    float z0 = p0.z, z1 = p1.z, z2 = p2.z;

    // ---- bbox in pixel space ----
    float Sf = (float)IMG_S;
    float minu = fminf(fminf(p0.x, p1.x), p2.x);
    float maxu = fmaxf(fmaxf(p0.x, p1.x), p2.x);
    float minv = fminf(fminf(p0.y, p1.y), p2.y);
    float maxv = fmaxf(fmaxf(p0.y, p1.y), p2.y);
    int x0 = max(0,         (int)floorf((minu * Sf + Sf - 1.0f) * 0.5f));
    int x1 = min(IMG_S - 1, (int)ceilf ((maxu * Sf + Sf - 1.0f) * 0.5f));
    int y0 = max(0,         (int)floorf((minv * Sf + Sf - 1.0f) * 0.5f));
    int y1 = min(IMG_S - 1, (int)ceilf ((maxv * Sf + Sf - 1.0f) * 0.5f));
    if (x0 > x1 || y0 > y1) return;

    int bw = x1 - x0 + 1;
    int bh = y1 - y0 + 1;
    int total = bw * bh;

    float e0x = p2.x - p1.x, e0y = p2.y - p1.y;   // edge(v1,v2)
    float e1x = p0.x - p2.x, e1y = p0.y - p2.y;   // edge(v2,v0)
    float e2x = p1.x - p0.x, e2y = p1.y - p0.y;   // edge(v0,v1)

    for (int i = lane; i < total; i += 32) {
        int x = x0 + (i % bw);
        int y = y0 + (i / bw);
        float px = (2.0f * x + 1.0f - Sf) / Sf;
        float py = (2.0f * y + 1.0f - Sf) / Sf;

        float w0 = e0x * (py - p1.y) - e0y * (px - p1.x);
        float w1 = e1x * (py - p2.y) - e1y * (px - p2.x);
        float w2 = e2x * (py - p0.y) - e2y * (px - p0.x);
        float area = w0 + w1 + w2;
        bool ok = fabsf(area) > 1e-10f;
        bool ins = ((w0 >= 0.0f && w1 >= 0.0f && w2 >= 0.0f) ||
                    (w0 <= 0.0f && w1 <= 0.0f && w2 <= 0.0f)) && ok;
        if (!ins) continue;
        float ia = 1.0f / area;
        float s = (w0 * ia) / z0 + (w1 * ia) / z1 + (w2 * ia) / z2 + 1e-12f;
        float zp = 1.0f / s;
        if (zp > Z_NEAR && zp < Z_FAR) {
            // inverted key: max(key) == lexicographic min of (z_bits, f).
            // empty == 0 (a hit can never be 0 since z_bits != 0xFFFFFFFF).
            unsigned long long key =
                ((unsigned long long)(~__float_as_uint(zp)) << 32) |
                (unsigned long long)(~(unsigned int)f);
            atomicMax(&g_zbuf[y * IMG_S + x], key);
        }
    }
}

// ---------------------------------------------------------------------------
__global__ void __launch_bounds__(NTHR, 2)
k_render(const float* __restrict__ verts,
         const int*   __restrict__ faces,
         const float* __restrict__ tex,
         const float* __restrict__ R,
         const float* __restrict__ t,
         const float* __restrict__ K,
         const float* __restrict__ Ldir,
         const float* __restrict__ idir_p,
         const float* __restrict__ iamb_p,
         const float* __restrict__ mimg,
         const float* __restrict__ mask,
         float* __restrict__ out,
         int F) {
    const int tid  = threadIdx.x;
    const int lane = tid & 31;
    const int wrp  = tid >> 5;
    const int bid  = blockIdx.x;
    const int gtid = bid * NTHR + tid;

    // ================= Phase A: raster (warp per face, strided) =============
    {
        float idir = idir_p[0];
        float iamb = iamb_p[0];
        int gwid = gtid >> 5;
        for (int f = gwid; f < F; f += NWARPS)
            raster_face(f, verts, faces, tex, R, t, K, Ldir, idir, iamb, lane);
    }

    grid_barrier(0);

    // ================= Phase B: resolve + block max / mask partial ==========
    {
        float gray = 0.0f, ms = 0.0f;
        int p = gtid;
        if (p < NPIX) {
            unsigned long long key = g_zbuf[p];
            float r = 0.0f, g = 0.0f, b = 0.0f;
            if (key != 0ull) {
                int f = (int)(~(unsigned int)(key & 0xFFFFFFFFull));
                float4 c = g_colors[f];
                r = c.x; g = c.y; b = c.z;
                g_zbuf[p] = 0ull;          // restore empty for next replay
            }
            out[1 + 0 * NPIX + p] = r;
            out[1 + 1 * NPIX + p] = g;
            out[1 + 2 * NPIX + p] = b;
            gray = r + g + b;
            g_gray[p] = gray;
            ms = mask[p];
        }
        float mx = gray;
        #pragma unroll
        for (int o = 16; o > 0; o >>= 1) {
            mx = fmaxf(mx, __shfl_down_sync(0xFFFFFFFFu, mx, o));
            ms += __shfl_down_sync(0xFFFFFFFFu, ms, o);
        }
        __shared__ float smx[16], sms[16];
        if (lane == 0) { smx[wrp] = mx; sms[wrp] = ms; }
        __syncthreads();
        if (tid == 0) {
            float m = smx[0], s = sms[0];
            #pragma unroll
            for (int w = 1; w < 16; w++) { m = fmaxf(m, smx[w]); s += sms[w]; }
            g_slot_max[bid] = m;
            g_slot_msk[bid] = s;
        }
    }

    grid_barrier(1);

    // ================= Phase C: loss partials (blocks 0..7) =================
    if (bid < LOSS_BLKS) {
        __shared__ float s_maxv;
        if (tid == 0) {
            float m = g_slot_max[0];
            for (int w = 1; w < NBLK; w++) m = fmaxf(m, g_slot_max[w]);
            s_maxv = m;
        }
        __syncthreads();
        float maxv = s_maxv;

        // exactly one float4 per thread: 8 blocks * 512 threads = 4096 = NPIX/4
        int i = bid * NTHR + tid;
        float4 gg = ((const float4*)g_gray)[i];
        float4 mm = ((const float4*)mimg)[i];
        float d0 = gg.x / maxv - mm.x;
        float d1 = gg.y / maxv - mm.y;
        float d2 = gg.z / maxv - mm.z;
        float d3 = gg.w / maxv - mm.w;
        float s1 = d0 * d0 + d1 * d1 + d2 * d2 + d3 * d3;

        #pragma unroll
        for (int o = 16; o > 0; o >>= 1)
            s1 += __shfl_down_sync(0xFFFFFFFFu, s1, o);
        __shared__ float sa[16];
        if (lane == 0) sa[wrp] = s1;
        __syncthreads();
        if (tid == 0) {
            float S = sa[0];
            #pragma unroll
            for (int w = 1; w < 16; w++) S += sa[w];
            g_slot_s1[bid] = S;
        }
    }

    grid_barrier(2);

    // ================= final: block 0 combines in fixed order ===============
    if (bid == 0 && tid == 0) {
        float S1 = g_slot_s1[0];
        #pragma unroll
        for (int w = 1; w < LOSS_BLKS; w++) S1 += g_slot_s1[w];
        float S2 = g_slot_msk[0];
        for (int w = 1; w < NBLK; w++) S2 += g_slot_msk[w];
        out[0] = S1 / S2;
    }
}

// ---------------------------------------------------------------------------
extern "C" void kernel_launch(void* const* d_in, const int* in_sizes, int n_in,
                              void* d_out, int out_size) {
    const float* verts = (const float*)d_in[0];
    const int*   faces = (const int*)  d_in[1];
    const float* tex   = (const float*)d_in[2];
    const float* R     = (const float*)d_in[3];
    const float* t     = (const float*)d_in[4];
    const float* K     = (const float*)d_in[5];
    const float* mimg  = (const float*)d_in[6];
    const float* mask  = (const float*)d_in[7];
    const float* Ldir  = (const float*)d_in[8];
    const float* idir  = (const float*)d_in[9];
    const float* iamb  = (const float*)d_in[10];
    float* out = (float*)d_out;

    int F = in_sizes[1] / 3;

    k_render<<<NBLK, NTHR>>>(verts, faces, tex, R, t, K, Ldir, idir, iamb,
                             mimg, mask, out, F);
}

// round 8
// speedup vs baseline: 1.0871x; 1.0871x over previous
#include <cuda_runtime.h>
#include <cstdint>

#define IMG_S 128
#define NPIX (IMG_S * IMG_S)
#define MAXF 4096
#define Z_NEAR 0.1f
#define Z_FAR 100.0f

#define RB 16          // resolve/loss block count (fixed partial slots)

// ---- scratch (zero-initialized at module load; resolve restores zeros) ----
__device__ unsigned long long g_zbuf[NPIX];   // 0 == empty (inverted keys)
__device__ float4 g_colors[MAXF];
__device__ float g_gray[NPIX];
__device__ int g_maxbits;            // gray max as float bits (idempotent across replays)
__device__ float g_slot_msk[RB];     // per-resolve-block mask partials
__device__ float g_slot_s1[RB];      // per-loss-block squared-diff partials
__device__ unsigned int g_ticket;    // loss completion ticket (self-resetting)

// ---------------------------------------------------------------------------
__device__ __forceinline__ float3 project_vert(float3 p,
                                               const float* __restrict__ R,
                                               const float* __restrict__ t,
                                               const float* __restrict__ K) {
    float vx = R[0] * p.x + R[1] * p.y + R[2] * p.z + t[0];
    float vy = R[3] * p.x + R[4] * p.y + R[5] * p.z + t[1];
    float vz = R[6] * p.x + R[7] * p.y + R[8] * p.z + t[2];
    float zd = vz + 1e-9f;
    float xn = vx / zd;
    float yn = vy / zd;
    float u = K[0] * xn + K[1] * yn + K[2];
    float v = K[3] * xn + K[4] * yn + K[5];
    float S = (float)IMG_S;
    float uu  = 2.0f * (u - S * 0.5f) / S;
    float vfl = S - v;
    float vvn = 2.0f * (vfl - S * 0.5f) / S;
    return make_float3(uu, vvn, vz);
}

// One warp per face: setup (redundant across lanes, cheap) + bbox raster.
__global__ void k_raster(const float* __restrict__ verts,
                         const int*   __restrict__ faces,
                         const float* __restrict__ tex,
                         const float* __restrict__ R,
                         const float* __restrict__ t,
                         const float* __restrict__ K,
                         const float* __restrict__ Ldir,
                         const float* __restrict__ idir_p,
                         const float* __restrict__ iamb_p,
                         int F) {
    int wid  = (blockIdx.x * blockDim.x + threadIdx.x) >> 5;
    int lane = threadIdx.x & 31;
    if (wid >= F) return;
    int f = wid;

    int i0 = faces[3 * f + 0];
    int i1 = faces[3 * f + 1];
    int i2 = faces[3 * f + 2];

    float3 A = make_float3(verts[3 * i0], verts[3 * i0 + 1], verts[3 * i0 + 2]);
    float3 B = make_float3(verts[3 * i1], verts[3 * i1 + 1], verts[3 * i1 + 2]);
    float3 C = make_float3(verts[3 * i2], verts[3 * i2 + 1], verts[3 * i2 + 2]);

    // ---- lighting (world space) ----
    float3 v10 = make_float3(A.x - B.x, A.y - B.y, A.z - B.z);
    float3 v12 = make_float3(C.x - B.x, C.y - B.y, C.z - B.z);
    float nx = v10.y * v12.z - v10.z * v12.y;
    float ny = v10.z * v12.x - v10.x * v12.z;
    float nz = v10.x * v12.y - v10.y * v12.x;
    float nrm = sqrtf(nx * nx + ny * ny + nz * nz);
    float inv = 1.0f / fmaxf(nrm, 1e-5f);
    nx *= inv; ny *= inv; nz *= inv;
    float cosv = fmaxf(0.0f, nx * Ldir[0] + ny * Ldir[1] + nz * Ldir[2]);
    float light = iamb_p[0] + idir_p[0] * cosv;
    if (lane == 0) {
        g_colors[f] = make_float4(tex[3 * f + 0] * light,
                                  tex[3 * f + 1] * light,
                                  tex[3 * f + 2] * light, 0.0f);
    }

    // ---- projection ----
    float3 p0 = project_vert(A, R, t, K);
    float3 p1 = project_vert(B, R, t, K);
    float3 p2 = project_vert(C, R, t, K);
    float z0 = p0.z, z1 = p1.z, z2 = p2.z;

    // ---- bbox in pixel space ----
    float Sf = (float)IMG_S;
    float minu = fminf(fminf(p0.x, p1.x), p2.x);
    float maxu = fmaxf(fmaxf(p0.x, p1.x), p2.x);
    float minv = fminf(fminf(p0.y, p1.y), p2.y);
    float maxv = fmaxf(fmaxf(p0.y, p1.y), p2.y);
    int x0 = max(0,         (int)floorf((minu * Sf + Sf - 1.0f) * 0.5f));
    int x1 = min(IMG_S - 1, (int)ceilf ((maxu * Sf + Sf - 1.0f) * 0.5f));
    int y0 = max(0,         (int)floorf((minv * Sf + Sf - 1.0f) * 0.5f));
    int y1 = min(IMG_S - 1, (int)ceilf ((maxv * Sf + Sf - 1.0f) * 0.5f));
    if (x0 > x1 || y0 > y1) return;

    int bw = x1 - x0 + 1;
    int bh = y1 - y0 + 1;
    int total = bw * bh;

    float e0x = p2.x - p1.x, e0y = p2.y - p1.y;   // edge(v1,v2)
    float e1x = p0.x - p2.x, e1y = p0.y - p2.y;   // edge(v2,v0)
    float e2x = p1.x - p0.x, e2y = p1.y - p0.y;   // edge(v0,v1)

    for (int i = lane; i < total; i += 32) {
        int x = x0 + (i % bw);
        int y = y0 + (i / bw);
        float px = (2.0f * x + 1.0f - Sf) / Sf;
        float py = (2.0f * y + 1.0f - Sf) / Sf;

        float w0 = e0x * (py - p1.y) - e0y * (px - p1.x);
        float w1 = e1x * (py - p2.y) - e1y * (px - p2.x);
        float w2 = e2x * (py - p0.y) - e2y * (px - p0.x);
        float area = w0 + w1 + w2;
        bool ok = fabsf(area) > 1e-10f;
        bool ins = ((w0 >= 0.0f && w1 >= 0.0f && w2 >= 0.0f) ||
                    (w0 <= 0.0f && w1 <= 0.0f && w2 <= 0.0f)) && ok;
        if (!ins) continue;
        float ia = 1.0f / area;
        float s = (w0 * ia) / z0 + (w1 * ia) / z1 + (w2 * ia) / z2 + 1e-12f;
        float zp = 1.0f / s;
        if (zp > Z_NEAR && zp < Z_FAR) {
            // inverted key: atomicMax == lexicographic min of (z_bits, f)
            // == argmin with first-index tie-break. empty == 0.
            unsigned long long key =
                ((unsigned long long)(~__float_as_uint(zp)) << 32) |
                (unsigned long long)(~(unsigned int)f);
            atomicMax(&g_zbuf[y * IMG_S + x], key);
        }
    }
}

// ---------------------------------------------------------------------------
// Resolve z-buffer -> RGB + gray; reset zbuf slot to 0 for the next replay;
// exact bitwise atomicMax for gray max; per-block mask partial to fixed slot.
__global__ void __launch_bounds__(1024)
k_resolve(float* __restrict__ out, const float* __restrict__ mask) {
    const int tid  = threadIdx.x;
    const int lane = tid & 31;
    const int wrp  = tid >> 5;
    const int p    = blockIdx.x * 1024 + tid;    // RB*1024 == NPIX

    unsigned long long key = g_zbuf[p];
    float r = 0.0f, g = 0.0f, b = 0.0f;
    if (key != 0ull) {
        int f = (int)(~(unsigned int)(key & 0xFFFFFFFFull));
        float4 c = g_colors[f];
        r = c.x; g = c.y; b = c.z;
        g_zbuf[p] = 0ull;                        // restore empty
    }
    out[1 + 0 * NPIX + p] = r;
    out[1 + 1 * NPIX + p] = g;
    out[1 + 2 * NPIX + p] = b;
    float gray = r + g + b;
    g_gray[p] = gray;

    float mx = gray;
    float ms = mask[p];
    #pragma unroll
    for (int o = 16; o > 0; o >>= 1) {
        mx = fmaxf(mx, __shfl_down_sync(0xFFFFFFFFu, mx, o));
        ms += __shfl_down_sync(0xFFFFFFFFu, ms, o);
    }
    __shared__ float smx[32], sms[32];
    if (lane == 0) { smx[wrp] = mx; sms[wrp] = ms; }
    __syncthreads();
    if (tid == 0) {
        float m = smx[0], s = sms[0];
        #pragma unroll
        for (int w = 1; w < 32; w++) { m = fmaxf(m, smx[w]); s += sms[w]; }
        atomicMax(&g_maxbits, __float_as_int(m));   // idempotent across replays
        g_slot_msk[blockIdx.x] = s;
    }
}

// ---------------------------------------------------------------------------
// 16 blocks x 256 threads: exactly one float4 per thread (single load round),
// fixed-slot partials; ticket-elected last block combines in fixed order.
__global__ void __launch_bounds__(256)
k_loss(const float* __restrict__ mimg, float* __restrict__ out) {
    const int tid  = threadIdx.x;
    const int lane = tid & 31;
    const int wrp  = tid >> 5;
    const float maxv = __int_as_float(g_maxbits);

    int i = blockIdx.x * 256 + tid;              // RB*256 == NPIX/4
    float4 gg = ((const float4*)g_gray)[i];
    float4 mm = ((const float4*)mimg)[i];
    float d0 = gg.x / maxv - mm.x;
    float d1 = gg.y / maxv - mm.y;
    float d2 = gg.z / maxv - mm.z;
    float d3 = gg.w / maxv - mm.w;
    float s1 = d0 * d0 + d1 * d1 + d2 * d2 + d3 * d3;

    #pragma unroll
    for (int o = 16; o > 0; o >>= 1)
        s1 += __shfl_down_sync(0xFFFFFFFFu, s1, o);
    __shared__ float sa[8];
    if (lane == 0) sa[wrp] = s1;
    __syncthreads();

    if (tid == 0) {
        float S = sa[0];
        #pragma unroll
        for (int w = 1; w < 8; w++) S += sa[w];
        g_slot_s1[blockIdx.x] = S;
        __threadfence();
        unsigned int tkt = atomicAdd(&g_ticket, 1u);
        if (tkt == RB - 1) {
            g_ticket = 0;                        // reset for next replay
            float S1 = g_slot_s1[0];
            #pragma unroll
            for (int w = 1; w < RB; w++) S1 += g_slot_s1[w];
            float S2 = g_slot_msk[0];
            #pragma unroll
            for (int w = 1; w < RB; w++) S2 += g_slot_msk[w];
            out[0] = S1 / S2;
        }
    }
}

// ---------------------------------------------------------------------------
extern "C" void kernel_launch(void* const* d_in, const int* in_sizes, int n_in,
                              void* d_out, int out_size) {
    const float* verts = (const float*)d_in[0];
    const int*   faces = (const int*)  d_in[1];
    const float* tex   = (const float*)d_in[2];
    const float* R     = (const float*)d_in[3];
    const float* t     = (const float*)d_in[4];
    const float* K     = (const float*)d_in[5];
    const float* mimg  = (const float*)d_in[6];
    const float* mask  = (const float*)d_in[7];
    const float* Ldir  = (const float*)d_in[8];
    const float* idir  = (const float*)d_in[9];
    const float* iamb  = (const float*)d_in[10];
    float* out = (float*)d_out;

    int F = in_sizes[1] / 3;

    int threads = 128;                        // 4 warps = 4 faces per block
    int blocks  = (F * 32 + threads - 1) / threads;
    k_raster<<<blocks, threads>>>(verts, faces, tex, R, t, K, Ldir, idir, iamb, F);
    k_resolve<<<RB, 1024>>>(out, mask);
    k_loss<<<RB, 256>>>(mimg, out);
}

// round 9
// speedup vs baseline: 1.5083x; 1.3874x over previous
#include <cuda_runtime.h>
#include <cstdint>

#define IMG_S 128
#define NPIX (IMG_S * IMG_S)
#define MAXF 4096
#define Z_NEAR 0.1f
#define Z_FAR 100.0f

#define RB 16            // resolve blocks: 16 x 1024 threads == NPIX

// ---- scratch (zero-initialized at module load; resolve restores zeros) ----
__device__ unsigned long long g_zbuf[NPIX];   // 0 == empty (inverted keys)
__device__ float4 g_colors[MAXF];
__device__ float g_gray[NPIX];
__device__ int g_maxbits;             // gray max bits (idempotent across replays)
__device__ float g_slot_msk[RB];      // fixed per-block mask partials
__device__ unsigned int g_ticket;     // self-resetting completion ticket

// ---------------------------------------------------------------------------
__device__ __forceinline__ float3 project_vert(float3 p,
                                               const float* __restrict__ R,
                                               const float* __restrict__ t,
                                               const float* __restrict__ K) {
    float vx = R[0] * p.x + R[1] * p.y + R[2] * p.z + t[0];
    float vy = R[3] * p.x + R[4] * p.y + R[5] * p.z + t[1];
    float vz = R[6] * p.x + R[7] * p.y + R[8] * p.z + t[2];
    float zd = vz + 1e-9f;
    float xn = vx / zd;
    float yn = vy / zd;
    float u = K[0] * xn + K[1] * yn + K[2];
    float v = K[3] * xn + K[4] * yn + K[5];
    float S = (float)IMG_S;
    float uu  = 2.0f * (u - S * 0.5f) / S;
    float vfl = S - v;
    float vvn = 2.0f * (vfl - S * 0.5f) / S;
    return make_float3(uu, vvn, vz);
}

// One warp per face: setup (warp-uniform -> issue-free redundancy) + bbox loop.
__global__ void k_raster(const float* __restrict__ verts,
                         const int*   __restrict__ faces,
                         const float* __restrict__ tex,
                         const float* __restrict__ R,
                         const float* __restrict__ t,
                         const float* __restrict__ K,
                         const float* __restrict__ Ldir,
                         const float* __restrict__ idir_p,
                         const float* __restrict__ iamb_p,
                         int F) {
    int wid  = (blockIdx.x * blockDim.x + threadIdx.x) >> 5;
    int lane = threadIdx.x & 31;
    if (wid >= F) return;
    int f = wid;

    int i0 = faces[3 * f + 0];
    int i1 = faces[3 * f + 1];
    int i2 = faces[3 * f + 2];

    float3 A = make_float3(verts[3 * i0], verts[3 * i0 + 1], verts[3 * i0 + 2]);
    float3 B = make_float3(verts[3 * i1], verts[3 * i1 + 1], verts[3 * i1 + 2]);
    float3 C = make_float3(verts[3 * i2], verts[3 * i2 + 1], verts[3 * i2 + 2]);

    // ---- lighting (world space) ----
    float3 v10 = make_float3(A.x - B.x, A.y - B.y, A.z - B.z);
    float3 v12 = make_float3(C.x - B.x, C.y - B.y, C.z - B.z);
    float nx = v10.y * v12.z - v10.z * v12.y;
    float ny = v10.z * v12.x - v10.x * v12.z;
    float nz = v10.x * v12.y - v10.y * v12.x;
    float nrm = sqrtf(nx * nx + ny * ny + nz * nz);
    float inv = 1.0f / fmaxf(nrm, 1e-5f);
    nx *= inv; ny *= inv; nz *= inv;
    float cosv = fmaxf(0.0f, nx * Ldir[0] + ny * Ldir[1] + nz * Ldir[2]);
    float light = iamb_p[0] + idir_p[0] * cosv;
    if (lane == 0) {
        g_colors[f] = make_float4(tex[3 * f + 0] * light,
                                  tex[3 * f + 1] * light,
                                  tex[3 * f + 2] * light, 0.0f);
    }

    // ---- projection ----
    float3 p0 = project_vert(A, R, t, K);
    float3 p1 = project_vert(B, R, t, K);
    float3 p2 = project_vert(C, R, t, K);

    // per-face z reciprocals (hoists 3 divisions out of the pixel loop;
    // <=1ulp extra rounding on each depth term, ~1e-7 relative on zp)
    float rz0 = 1.0f / p0.z;
    float rz1 = 1.0f / p1.z;
    float rz2 = 1.0f / p2.z;

    // ---- bbox in pixel space ----
    float Sf = (float)IMG_S;
    float minu = fminf(fminf(p0.x, p1.x), p2.x);
    float maxu = fmaxf(fmaxf(p0.x, p1.x), p2.x);
    float minv = fminf(fminf(p0.y, p1.y), p2.y);
    float maxv = fmaxf(fmaxf(p0.y, p1.y), p2.y);
    int x0 = max(0,         (int)floorf((minu * Sf + Sf - 1.0f) * 0.5f));
    int x1 = min(IMG_S - 1, (int)ceilf ((maxu * Sf + Sf - 1.0f) * 0.5f));
    int y0 = max(0,         (int)floorf((minv * Sf + Sf - 1.0f) * 0.5f));
    int y1 = min(IMG_S - 1, (int)ceilf ((maxv * Sf + Sf - 1.0f) * 0.5f));
    if (x0 > x1 || y0 > y1) return;

    int bw = x1 - x0 + 1;
    int bh = y1 - y0 + 1;
    int total = bw * bh;

    float e0x = p2.x - p1.x, e0y = p2.y - p1.y;   // edge(v1,v2)
    float e1x = p0.x - p2.x, e1y = p0.y - p2.y;   // edge(v2,v0)
    float e2x = p1.x - p0.x, e2y = p1.y - p0.y;   // edge(v0,v1)

    for (int i = lane; i < total; i += 32) {
        int x = x0 + (i % bw);
        int y = y0 + (i / bw);
        float px = (2.0f * x + 1.0f - Sf) / Sf;
        float py = (2.0f * y + 1.0f - Sf) / Sf;

        // exact reference algebra for the sign tests
        float w0 = e0x * (py - p1.y) - e0y * (px - p1.x);
        float w1 = e1x * (py - p2.y) - e1y * (px - p2.x);
        float w2 = e2x * (py - p0.y) - e2y * (px - p0.x);
        float area = w0 + w1 + w2;
        bool ok = fabsf(area) > 1e-10f;
        bool ins = ((w0 >= 0.0f && w1 >= 0.0f && w2 >= 0.0f) ||
                    (w0 <= 0.0f && w1 <= 0.0f && w2 <= 0.0f)) && ok;
        if (!ins) continue;
        float ia = 1.0f / area;
        float s = (w0 * ia) * rz0 + (w1 * ia) * rz1 + (w2 * ia) * rz2 + 1e-12f;
        float zp = 1.0f / s;
        if (zp > Z_NEAR && zp < Z_FAR) {
            // inverted key: atomicMax == lexicographic min of (z_bits, f)
            // == argmin with first-index tie-break. empty == 0.
            unsigned long long key =
                ((unsigned long long)(~__float_as_uint(zp)) << 32) |
                (unsigned long long)(~(unsigned int)f);
            atomicMax(&g_zbuf[y * IMG_S + x], key);
        }
    }
}

// ---------------------------------------------------------------------------
// Fused: resolve -> RGB/gray (+zbuf reset), exact bitwise gray max, fixed-slot
// mask partials; threadfence + ticket; last block computes the loss over the
// full (L2-resident) gray/mimg in fixed order -> deterministic.
__global__ void __launch_bounds__(1024)
k_resolve_loss(float* __restrict__ out,
               const float* __restrict__ mimg,
               const float* __restrict__ mask) {
    const int tid  = threadIdx.x;
    const int lane = tid & 31;
    const int wrp  = tid >> 5;
    const int p    = blockIdx.x * 1024 + tid;    // RB*1024 == NPIX

    // ---- resolve ----
    unsigned long long key = g_zbuf[p];
    float r = 0.0f, g = 0.0f, b = 0.0f;
    if (key != 0ull) {
        int f = (int)(~(unsigned int)(key & 0xFFFFFFFFull));
        float4 c = g_colors[f];
        r = c.x; g = c.y; b = c.z;
        g_zbuf[p] = 0ull;                        // restore empty for next replay
    }
    out[1 + 0 * NPIX + p] = r;
    out[1 + 1 * NPIX + p] = g;
    out[1 + 2 * NPIX + p] = b;
    float gray = r + g + b;
    g_gray[p] = gray;

    // ---- block max + mask partial ----
    float mx = gray;
    float ms = mask[p];
    #pragma unroll
    for (int o = 16; o > 0; o >>= 1) {
        mx = fmaxf(mx, __shfl_down_sync(0xFFFFFFFFu, mx, o));
        ms += __shfl_down_sync(0xFFFFFFFFu, ms, o);
    }
    __shared__ float smx[32], sms[32];
    if (lane == 0) { smx[wrp] = mx; sms[wrp] = ms; }
    __syncthreads();
    if (tid == 0) {
        float m = smx[0], s = sms[0];
        #pragma unroll
        for (int w = 1; w < 32; w++) { m = fmaxf(m, smx[w]); s += sms[w]; }
        atomicMax(&g_maxbits, __float_as_int(m));
        g_slot_msk[blockIdx.x] = s;
    }

    // ---- completion ticket (threadFenceReduction pattern) ----
    __threadfence();
    __shared__ bool is_last;
    if (tid == 0) {
        unsigned int tkt = atomicAdd(&g_ticket, 1u);
        is_last = (tkt == RB - 1);
    }
    __syncthreads();
    if (!is_last) return;
    if (tid == 0) g_ticket = 0;                  // reset for next replay
    __threadfence();

    // ---- last block: loss over full image, fixed order ----
    float maxv = __int_as_float(g_maxbits);
    const float4* g4 = (const float4*)g_gray;
    const float4* m4 = (const float4*)mimg;

    float s1 = 0.0f;
    #pragma unroll
    for (int i = tid; i < NPIX / 4; i += 1024) {
        float4 gg = g4[i];
        float4 mm = m4[i];
        float d0 = gg.x / maxv - mm.x;
        float d1 = gg.y / maxv - mm.y;
        float d2 = gg.z / maxv - mm.z;
        float d3 = gg.w / maxv - mm.w;
        s1 += d0 * d0 + d1 * d1 + d2 * d2 + d3 * d3;
    }
    #pragma unroll
    for (int o = 16; o > 0; o >>= 1)
        s1 += __shfl_down_sync(0xFFFFFFFFu, s1, o);
    __shared__ float sa[32];
    if (lane == 0) sa[wrp] = s1;
    __syncthreads();
    if (tid == 0) {
        float S1 = sa[0];
        #pragma unroll
        for (int w = 1; w < 32; w++) S1 += sa[w];
        float S2 = g_slot_msk[0];
        #pragma unroll
        for (int w = 1; w < RB; w++) S2 += g_slot_msk[w];
        out[0] = S1 / S2;
    }
}

// ---------------------------------------------------------------------------
extern "C" void kernel_launch(void* const* d_in, const int* in_sizes, int n_in,
                              void* d_out, int out_size) {
    const float* verts = (const float*)d_in[0];
    const int*   faces = (const int*)  d_in[1];
    const float* tex   = (const float*)d_in[2];
    const float* R     = (const float*)d_in[3];
    const float* t     = (const float*)d_in[4];
    const float* K     = (const float*)d_in[5];
    const float* mimg  = (const float*)d_in[6];
    const float* mask  = (const float*)d_in[7];
    const float* Ldir  = (const float*)d_in[8];
    const float* idir  = (const float*)d_in[9];
    const float* iamb  = (const float*)d_in[10];
    float* out = (float*)d_out;

    int F = in_sizes[1] / 3;

    int threads = 128;                        // 4 warps = 4 faces per block
    int blocks  = (F * 32 + threads - 1) / threads;
    k_raster<<<blocks, threads>>>(verts, faces, tex, R, t, K, Ldir, idir, iamb, F);
    k_resolve_loss<<<RB, 1024>>>(out, mimg, mask);
}

// round 10
// speedup vs baseline: 1.6237x; 1.0765x over previous
#include <cuda_runtime.h>
#include <cstdint>

#define IMG_S 128
#define NPIX (IMG_S * IMG_S)
#define MAXF 4096
#define Z_NEAR 0.1f
#define Z_FAR 100.0f

#define RB 64            // resolve blocks: 64 x 256 threads == NPIX

// ---- scratch (zero-initialized at module load; resolve restores zeros) ----
__device__ unsigned long long g_zbuf[NPIX];   // 0 == empty (inverted keys)
__device__ float4 g_colors[MAXF];
__device__ int g_maxbits;             // gray max bits (idempotent across replays)
__device__ float g_slot_g2[RB];       // per-block sum gray^2
__device__ float g_slot_gm[RB];       // per-block sum gray*mimg
__device__ float g_slot_m2[RB];       // per-block sum mimg^2
__device__ float g_slot_msk[RB];      // per-block sum mask
__device__ unsigned int g_ticket;     // self-resetting completion ticket

// ---------------------------------------------------------------------------
__device__ __forceinline__ float3 project_vert(float3 p,
                                               const float* __restrict__ R,
                                               const float* __restrict__ t,
                                               const float* __restrict__ K) {
    float vx = R[0] * p.x + R[1] * p.y + R[2] * p.z + t[0];
    float vy = R[3] * p.x + R[4] * p.y + R[5] * p.z + t[1];
    float vz = R[6] * p.x + R[7] * p.y + R[8] * p.z + t[2];
    float zd = vz + 1e-9f;
    float xn = vx / zd;
    float yn = vy / zd;
    float u = K[0] * xn + K[1] * yn + K[2];
    float v = K[3] * xn + K[4] * yn + K[5];
    float S = (float)IMG_S;
    float uu  = 2.0f * (u - S * 0.5f) / S;
    float vfl = S - v;
    float vvn = 2.0f * (vfl - S * 0.5f) / S;
    return make_float3(uu, vvn, vz);
}

// One warp per face: setup (warp-uniform -> broadcast loads) + bbox loop.
__global__ void k_raster(const float* __restrict__ verts,
                         const int*   __restrict__ faces,
                         const float* __restrict__ tex,
                         const float* __restrict__ R,
                         const float* __restrict__ t,
                         const float* __restrict__ K,
                         const float* __restrict__ Ldir,
                         const float* __restrict__ idir_p,
                         const float* __restrict__ iamb_p,
                         int F) {
    int wid  = (blockIdx.x * blockDim.x + threadIdx.x) >> 5;
    int lane = threadIdx.x & 31;
    if (wid >= F) return;
    int f = wid;

    int i0 = faces[3 * f + 0];
    int i1 = faces[3 * f + 1];
    int i2 = faces[3 * f + 2];

    float3 A = make_float3(verts[3 * i0], verts[3 * i0 + 1], verts[3 * i0 + 2]);
    float3 B = make_float3(verts[3 * i1], verts[3 * i1 + 1], verts[3 * i1 + 2]);
    float3 C = make_float3(verts[3 * i2], verts[3 * i2 + 1], verts[3 * i2 + 2]);

    // ---- lighting (world space) ----
    float3 v10 = make_float3(A.x - B.x, A.y - B.y, A.z - B.z);
    float3 v12 = make_float3(C.x - B.x, C.y - B.y, C.z - B.z);
    float nx = v10.y * v12.z - v10.z * v12.y;
    float ny = v10.z * v12.x - v10.x * v12.z;
    float nz = v10.x * v12.y - v10.y * v12.x;
    float nrm = sqrtf(nx * nx + ny * ny + nz * nz);
    float inv = 1.0f / fmaxf(nrm, 1e-5f);
    nx *= inv; ny *= inv; nz *= inv;
    float cosv = fmaxf(0.0f, nx * Ldir[0] + ny * Ldir[1] + nz * Ldir[2]);
    float light = iamb_p[0] + idir_p[0] * cosv;
    if (lane == 0) {
        g_colors[f] = make_float4(tex[3 * f + 0] * light,
                                  tex[3 * f + 1] * light,
                                  tex[3 * f + 2] * light, 0.0f);
    }

    // ---- projection (exact reference algebra) ----
    float3 p0 = project_vert(A, R, t, K);
    float3 p1 = project_vert(B, R, t, K);
    float3 p2 = project_vert(C, R, t, K);

    // per-face z reciprocals (hoists 3 divisions out of the pixel loop)
    float rz0 = 1.0f / p0.z;
    float rz1 = 1.0f / p1.z;
    float rz2 = 1.0f / p2.z;

    // ---- bbox in pixel space ----
    float Sf = (float)IMG_S;
    float minu = fminf(fminf(p0.x, p1.x), p2.x);
    float maxu = fmaxf(fmaxf(p0.x, p1.x), p2.x);
    float minv = fminf(fminf(p0.y, p1.y), p2.y);
    float maxv = fmaxf(fmaxf(p0.y, p1.y), p2.y);
    int x0 = max(0,         (int)floorf((minu * Sf + Sf - 1.0f) * 0.5f));
    int x1 = min(IMG_S - 1, (int)ceilf ((maxu * Sf + Sf - 1.0f) * 0.5f));
    int y0 = max(0,         (int)floorf((minv * Sf + Sf - 1.0f) * 0.5f));
    int y1 = min(IMG_S - 1, (int)ceilf ((maxv * Sf + Sf - 1.0f) * 0.5f));
    if (x0 > x1 || y0 > y1) return;

    int bw = x1 - x0 + 1;
    int bh = y1 - y0 + 1;
    int total = bw * bh;

    float e0x = p2.x - p1.x, e0y = p2.y - p1.y;   // edge(v1,v2)
    float e1x = p0.x - p2.x, e1y = p0.y - p2.y;   // edge(v2,v0)
    float e2x = p1.x - p0.x, e2y = p1.y - p0.y;   // edge(v0,v1)

    for (int i = lane; i < total; i += 32) {
        int x = x0 + (i % bw);
        int y = y0 + (i / bw);
        float px = (2.0f * x + 1.0f - Sf) / Sf;
        float py = (2.0f * y + 1.0f - Sf) / Sf;

        // exact reference algebra for the sign tests
        float w0 = e0x * (py - p1.y) - e0y * (px - p1.x);
        float w1 = e1x * (py - p2.y) - e1y * (px - p2.x);
        float w2 = e2x * (py - p0.y) - e2y * (px - p0.x);
        float area = w0 + w1 + w2;
        bool ok = fabsf(area) > 1e-10f;
        bool ins = ((w0 >= 0.0f && w1 >= 0.0f && w2 >= 0.0f) ||
                    (w0 <= 0.0f && w1 <= 0.0f && w2 <= 0.0f)) && ok;
        if (!ins) continue;
        float ia = 1.0f / area;
        float s = (w0 * ia) * rz0 + (w1 * ia) * rz1 + (w2 * ia) * rz2 + 1e-12f;
        float zp = 1.0f / s;
        if (zp > Z_NEAR && zp < Z_FAR) {
            // inverted key: atomicMax == lexicographic min of (z_bits, f)
            // == argmin with first-index tie-break. empty == 0.
            unsigned long long key =
                ((unsigned long long)(~__float_as_uint(zp)) << 32) |
                (unsigned long long)(~(unsigned int)f);
            atomicMax(&g_zbuf[y * IMG_S + x], key);
        }
    }
}

// ---------------------------------------------------------------------------
// Single-pass fused epilogue. Loss via algebraic expansion:
//   sum (g/maxv - m)^2 = (sum g^2)/maxv^2 - 2 (sum g*m)/maxv + sum m^2
// so per-block partials need no maxv -> no second image pass. Deterministic:
// fixed slots, fixed combine order, exact bitwise max.
__global__ void __launch_bounds__(256)
k_resolve_loss(float* __restrict__ out,
               const float* __restrict__ mimg,
               const float* __restrict__ mask) {
    const int tid  = threadIdx.x;
    const int lane = tid & 31;
    const int wrp  = tid >> 5;
    const int p    = blockIdx.x * 256 + tid;     // RB*256 == NPIX

    // ---- resolve ----
    unsigned long long key = g_zbuf[p];
    float r = 0.0f, g = 0.0f, b = 0.0f;
    if (key != 0ull) {
        int f = (int)(~(unsigned int)(key & 0xFFFFFFFFull));
        float4 c = g_colors[f];
        r = c.x; g = c.y; b = c.z;
        g_zbuf[p] = 0ull;                        // restore empty for next replay
    }
    out[1 + 0 * NPIX + p] = r;
    out[1 + 1 * NPIX + p] = g;
    out[1 + 2 * NPIX + p] = b;
    float gray = r + g + b;
    float m    = mimg[p];
    float mk   = mask[p];

    // ---- block reductions: max, g^2, g*m, m^2, mask ----
    float mx  = gray;
    float g2  = gray * gray;
    float gm  = gray * m;
    float m2  = m * m;
    #pragma unroll
    for (int o = 16; o > 0; o >>= 1) {
        mx += 0.0f; // keep separate dependency chains readable
        mx  = fmaxf(mx, __shfl_down_sync(0xFFFFFFFFu, mx, o));
        g2 += __shfl_down_sync(0xFFFFFFFFu, g2, o);
        gm += __shfl_down_sync(0xFFFFFFFFu, gm, o);
        m2 += __shfl_down_sync(0xFFFFFFFFu, m2, o);
        mk += __shfl_down_sync(0xFFFFFFFFu, mk, o);
    }
    __shared__ float smx[8], sg2[8], sgm[8], sm2[8], smk[8];
    if (lane == 0) { smx[wrp] = mx; sg2[wrp] = g2; sgm[wrp] = gm;
                     sm2[wrp] = m2; smk[wrp] = mk; }
    __syncthreads();
    if (tid == 0) {
        float a = smx[0], s2 = sg2[0], sm = sgm[0], s3 = sm2[0], s4 = smk[0];
        #pragma unroll
        for (int w = 1; w < 8; w++) {
            a  = fmaxf(a, smx[w]);
            s2 += sg2[w]; sm += sgm[w]; s3 += sm2[w]; s4 += smk[w];
        }
        atomicMax(&g_maxbits, __float_as_int(a));
        g_slot_g2[blockIdx.x]  = s2;
        g_slot_gm[blockIdx.x]  = sm;
        g_slot_m2[blockIdx.x]  = s3;
        g_slot_msk[blockIdx.x] = s4;
        __threadfence();
        unsigned int tkt = atomicAdd(&g_ticket, 1u);
        if (tkt == RB - 1) {
            g_ticket = 0;                        // reset for next replay
            float A = g_slot_g2[0], Bq = g_slot_gm[0];
            float C = g_slot_m2[0], M = g_slot_msk[0];
            #pragma unroll
            for (int w = 1; w < RB; w++) {
                A += g_slot_g2[w]; Bq += g_slot_gm[w];
                C += g_slot_m2[w]; M  += g_slot_msk[w];
            }
            float maxv = __int_as_float(g_maxbits);
            float S1 = A / (maxv * maxv) - 2.0f * Bq / maxv + C;
            out[0] = S1 / M;
        }
    }
}

// ---------------------------------------------------------------------------
extern "C" void kernel_launch(void* const* d_in, const int* in_sizes, int n_in,
                              void* d_out, int out_size) {
    const float* verts = (const float*)d_in[0];
    const int*   faces = (const int*)  d_in[1];
    const float* tex   = (const float*)d_in[2];
    const float* R     = (const float*)d_in[3];
    const float* t     = (const float*)d_in[4];
    const float* K     = (const float*)d_in[5];
    const float* mimg  = (const float*)d_in[6];
    const float* mask  = (const float*)d_in[7];
    const float* Ldir  = (const float*)d_in[8];
    const float* idir  = (const float*)d_in[9];
    const float* iamb  = (const float*)d_in[10];
    float* out = (float*)d_out;

    int F = in_sizes[1] / 3;

    int threads = 128;                        // 4 warps = 4 faces per block
    int blocks  = (F * 32 + threads - 1) / threads;
    k_raster<<<blocks, threads>>>(verts, faces, tex, R, t, K, Ldir, idir, iamb, F);
    k_resolve_loss<<<RB, 256>>>(out, mimg, mask);
}